// round 8
// baseline (speedup 1.0000x reference)
#include <cuda_runtime.h>
#include <cuda_fp16.h>
#include <cstdint>

#define B_   64
#define P_   2304
#define SD_  1024
#define EPSQ 1e-7f

// ---------------- scratch ----------------
__device__ __half g_Wh[(size_t)P_ * SD_ * 16];   // [p][sd][k'] fp16 (75.5 MB, L2-resident)
__device__ __half g_uh[P_ * B_ * 16];            // [p][b][k'] fp16 (4.7 MB)
__device__ float  g_ws[SD_ * B_];
__device__ float  g_v [SD_ * B_];
__device__ float  g_logits[P_ * 32];
__device__ float  g_rw    [P_ * 32];

// k-permutation: pos(k) groups (2q,2q+1,2q+8,2q+9) contiguously so each
// mma fragment reg-pair is one 8-byte load.
__device__ __forceinline__ int kperm(int k) {
    return (k < 8) ? (((k >> 1) << 2) | (k & 1))
                   : ((((k - 8) >> 1) << 2) | 2 | (k & 1));
}

__device__ __forceinline__ void hmma16816(float* d,
                                          uint32_t a0, uint32_t a1, uint32_t a2, uint32_t a3,
                                          uint32_t b0, uint32_t b1,
                                          float c0, float c1, float c2, float c3) {
    asm volatile(
        "mma.sync.aligned.m16n8k16.row.col.f32.f16.f16.f32 "
        "{%0,%1,%2,%3}, {%4,%5,%6,%7}, {%8,%9}, {%10,%11,%12,%13};"
        : "=f"(d[0]), "=f"(d[1]), "=f"(d[2]), "=f"(d[3])
        : "r"(a0), "r"(a1), "r"(a2), "r"(a3), "r"(b0), "r"(b1),
          "f"(c0), "f"(c1), "f"(c2), "f"(c3));
}

// ---------------- tiny kernels ----------------
__global__ void zero_logits_kernel() {
    int i = blockIdx.x * blockDim.x + threadIdx.x;
    if (i < P_ * 32) g_logits[i] = 0.f;
}
__global__ void zero_ws_kernel() {
    int i = blockIdx.x * blockDim.x + threadIdx.x;
    g_ws[i] = 0.f;
}

// ---------------- u = squash(caps) over D1 -> g_uh[p][b][k'] fp16 ----------------
__global__ void squash_u_kernel(const float* __restrict__ caps) {
    int gid = blockIdx.x * blockDim.x + threadIdx.x;   // p*64+b
    int p = gid >> 6, b = gid & 63;
    const float4* src = (const float4*)(caps + ((size_t)b * P_ + p) * 16);
    float4 a0 = src[0], a1 = src[1], a2 = src[2], a3 = src[3];
    float x[16] = {a0.x,a0.y,a0.z,a0.w, a1.x,a1.y,a1.z,a1.w,
                   a2.x,a2.y,a2.z,a2.w, a3.x,a3.y,a3.z,a3.w};
    float sq = 0.f;
    #pragma unroll
    for (int k = 0; k < 16; k++) sq += x[k] * x[k];
    float sc = (sq / (1.f + sq)) / sqrtf(sq + EPSQ);
    __half h[16];
    #pragma unroll
    for (int k = 0; k < 16; k++) h[kperm(k)] = __float2half(x[k] * sc);
    uint4* dst = (uint4*)(g_uh + (size_t)gid * 16);
    dst[0] = ((uint4*)h)[0];
    dst[1] = ((uint4*)h)[1];
}

// ---------------- W fp32 -> fp16 k-permuted (once) ----------------
__global__ void convert_w_kernel(const float* __restrict__ W) {
    int gid = blockIdx.x * blockDim.x + threadIdx.x;   // (p,sd)
    const float4* src = (const float4*)(W + (size_t)gid * 16);
    float4 f0 = src[0], f1 = src[1], f2 = src[2], f3 = src[3];
    float x[16] = {f0.x,f0.y,f0.z,f0.w, f1.x,f1.y,f1.z,f1.w,
                   f2.x,f2.y,f2.z,f2.w, f3.x,f3.y,f3.z,f3.w};
    __half h[16];
    #pragma unroll
    for (int k = 0; k < 16; k++) h[kperm(k)] = __float2half(x[k]);
    uint4* dst = (uint4*)(g_Wh + (size_t)gid * 16);
    dst[0] = ((uint4*)h)[0];
    dst[1] = ((uint4*)h)[1];
}

// ---------------- softmax over S ----------------
__global__ void softmax_kernel() {
    int p    = blockIdx.x * 8 + (threadIdx.x >> 5);
    int lane = threadIdx.x & 31;
    float x = g_logits[p * 32 + lane];
    float m = x;
    #pragma unroll
    for (int o = 16; o; o >>= 1) m = fmaxf(m, __shfl_xor_sync(0xffffffffu, m, o));
    float e = expf(x - m);
    float sum = e;
    #pragma unroll
    for (int o = 16; o; o >>= 1) sum += __shfl_xor_sync(0xffffffffu, sum, o);
    g_rw[p * 32 + lane] = e / sum;
}

// ---------------- fused ws: acc += rw[p,s] * (W_p @ u_p^T), no preds array ----------------
// grid (8 sd-blocks, 18 p-chunks), 256 thr. Warp owns 16 sd rows (one s).
__global__ void __launch_bounds__(256) ws_kernel() {
    int tid = threadIdx.x, wid = tid >> 5, lane = tid & 31;
    int r = lane >> 2, q = lane & 3;
    int sdb = blockIdx.x, chunk = blockIdx.y;
    int s_w = sdb * 4 + (wid >> 1);
    int sd0 = sdb * 128 + wid * 16;

    float acc[8][4];
    #pragma unroll
    for (int j = 0; j < 8; j++)
        acc[j][0] = acc[j][1] = acc[j][2] = acc[j][3] = 0.f;

    const __half* wbase = g_Wh + (size_t)(sd0 + r) * 16 + 4 * q;
    const __half* ubase = g_uh + (size_t)r * 16 + 4 * q;

    #pragma unroll 2
    for (int i = 0; i < 128; i++) {
        int p = chunk * 128 + i;
        float rw = __ldg(&g_rw[p * 32 + s_w]);
        const __half* wp = wbase + (size_t)p * (SD_ * 16);
        uint2 t0 = *(const uint2*)(wp);
        uint2 t1 = *(const uint2*)(wp + 128);          // +8 sd rows
        const __half* up = ubase + (size_t)p * (64 * 16);
        #pragma unroll
        for (int j = 0; j < 8; j++) {
            uint2 tb = *(const uint2*)(up + j * 128);  // b rows j*8+r
            float d[4];
            hmma16816(d, t0.x, t1.x, t0.y, t1.y, tb.x, tb.y, 0.f, 0.f, 0.f, 0.f);
            acc[j][0] += rw * d[0]; acc[j][1] += rw * d[1];
            acc[j][2] += rw * d[2]; acc[j][3] += rw * d[3];
        }
    }
    #pragma unroll
    for (int j = 0; j < 8; j++) {
        int b = j * 8 + 2 * q;
        atomicAdd(&g_ws[(sd0 + r    ) * 64 + b    ], acc[j][0]);
        atomicAdd(&g_ws[(sd0 + r    ) * 64 + b + 1], acc[j][1]);
        atomicAdd(&g_ws[(sd0 + r + 8) * 64 + b    ], acc[j][2]);
        atomicAdd(&g_ws[(sd0 + r + 8) * 64 + b + 1], acc[j][3]);
    }
}

// ---------------- v = squash(ws) over D2 ----------------
__global__ void squash_v_kernel() {
    int gid = blockIdx.x * blockDim.x + threadIdx.x;   // 0..2047
    int s = gid >> 6, b = gid & 63;
    float x[32]; float sq = 0.f;
    #pragma unroll
    for (int d = 0; d < 32; d++) { x[d] = g_ws[(s * 32 + d) * B_ + b]; sq += x[d] * x[d]; }
    float sc = (sq / (1.f + sq)) / sqrtf(sq + EPSQ);
    #pragma unroll
    for (int d = 0; d < 32; d++) g_v[(s * 32 + d) * B_ + b] = x[d] * sc;
}

// ---------------- fused agree: logits[p,s] += (1/B) sum preds.v, preds recomputed ----------------
__global__ void __launch_bounds__(256) agree_kernel() {
    int tid = threadIdx.x, wid = tid >> 5, lane = tid & 31;
    int r = lane >> 2, q = lane & 3;
    int sdb = blockIdx.x, chunk = blockIdx.y;
    int s_w = sdb * 4 + (wid >> 1);
    int sd0 = sdb * 128 + wid * 16;

    // v slice in fragment layout (register-resident for the whole p loop)
    float vf[8][4];
    #pragma unroll
    for (int j = 0; j < 8; j++) {
        int b = j * 8 + 2 * q;
        float2 v0 = *(const float2*)&g_v[(sd0 + r    ) * 64 + b];
        float2 v1 = *(const float2*)&g_v[(sd0 + r + 8) * 64 + b];
        vf[j][0] = v0.x; vf[j][1] = v0.y; vf[j][2] = v1.x; vf[j][3] = v1.y;
    }

    const __half* wbase = g_Wh + (size_t)(sd0 + r) * 16 + 4 * q;
    const __half* ubase = g_uh + (size_t)r * 16 + 4 * q;

    #pragma unroll 2
    for (int i = 0; i < 128; i++) {
        int p = chunk * 128 + i;
        const __half* wp = wbase + (size_t)p * (SD_ * 16);
        uint2 t0 = *(const uint2*)(wp);
        uint2 t1 = *(const uint2*)(wp + 128);
        const __half* up = ubase + (size_t)p * (64 * 16);
        float s = 0.f;
        #pragma unroll
        for (int j = 0; j < 8; j++) {
            uint2 tb = *(const uint2*)(up + j * 128);
            float d[4];
            hmma16816(d, t0.x, t1.x, t0.y, t1.y, tb.x, tb.y, 0.f, 0.f, 0.f, 0.f);
            s += d[0] * vf[j][0] + d[1] * vf[j][1] + d[2] * vf[j][2] + d[3] * vf[j][3];
        }
        #pragma unroll
        for (int o = 16; o; o >>= 1) s += __shfl_xor_sync(0xffffffffu, s, o);
        if (lane == 0) atomicAdd(&g_logits[p * 32 + s_w], s * (1.f / 64.f));
    }
}

// ---------------- final squash -> out[b][s][d] ----------------
__global__ void final_kernel(float* __restrict__ out) {
    int gid = blockIdx.x * blockDim.x + threadIdx.x;
    int s = gid >> 6, b = gid & 63;
    float x[32]; float sq = 0.f;
    #pragma unroll
    for (int d = 0; d < 32; d++) { x[d] = g_ws[(s * 32 + d) * B_ + b]; sq += x[d] * x[d]; }
    float sc = (sq / (1.f + sq)) / sqrtf(sq + EPSQ);
    #pragma unroll
    for (int d = 0; d < 32; d++) out[(b * 32 + s) * 32 + d] = x[d] * sc;
}

// ---------------- launch ----------------
extern "C" void kernel_launch(void* const* d_in, const int* in_sizes, int n_in,
                              void* d_out, int out_size) {
    const float* caps = (const float*)d_in[0];   // [B,P,D1] fp32
    const float* W    = (const float*)d_in[1];   // [P,S,D2,D1] fp32
    float* out        = (float*)d_out;           // [B,1,S,D2] fp32

    zero_logits_kernel<<<(P_ * 32) / 256, 256>>>();
    squash_u_kernel<<<(P_ * B_) / 256, 256>>>(caps);
    convert_w_kernel<<<(P_ * SD_) / 256, 256>>>(W);

    for (int it = 0; it < 3; it++) {
        softmax_kernel<<<P_ / 8, 256>>>();
        zero_ws_kernel<<<(SD_ * B_) / 256, 256>>>();
        ws_kernel<<<dim3(8, 18), 256>>>();
        if (it < 2) {
            squash_v_kernel<<<8, 256>>>();
            agree_kernel<<<dim3(8, 18), 256>>>();
        } else {
            final_kernel<<<8, 256>>>(out);
        }
    }
}

// round 9
// speedup vs baseline: 2.2424x; 2.2424x over previous
#include <cuda_runtime.h>
#include <cuda_fp16.h>
#include <cstdint>

#define B_   64
#define P_   2304
#define SD_  1024
#define NCH  36            // p-chunks (64 p each)
#define EPSQ 1e-7f

// ---------------- scratch ----------------
__device__ __half g_Wh[(size_t)P_ * SD_ * 16];     // [p][sd][k'] fp16 (75.5 MB)
__device__ __half g_uh[P_ * B_ * 16];              // [p][b][k'] fp16 (4.7 MB)
__device__ float  g_wspart[(size_t)NCH * SD_ * B_];// per-chunk ws partials (9.4 MB)
__device__ float  g_agree[2][P_ * 32];             // per-warp-parity agree partials
__device__ float  g_ws[SD_ * B_];
__device__ float  g_v [SD_ * B_];
__device__ float  g_logits[P_ * 32];
__device__ float  g_rw    [P_ * 32];

// k-permutation: groups (2q,2q+1,2q+8,2q+9) contiguously -> fragment pair = one LDG.64
__device__ __forceinline__ int kperm(int k) {
    return (k < 8) ? (((k >> 1) << 2) | (k & 1))
                   : ((((k - 8) >> 1) << 2) | 2 | (k & 1));
}

__device__ __forceinline__ void hmma16816(float* d,
                                          uint32_t a0, uint32_t a1, uint32_t a2, uint32_t a3,
                                          uint32_t b0, uint32_t b1) {
    asm volatile(
        "mma.sync.aligned.m16n8k16.row.col.f32.f16.f16.f32 "
        "{%0,%1,%2,%3}, {%4,%5,%6,%7}, {%8,%9}, {%10,%11,%12,%13};"
        : "=f"(d[0]), "=f"(d[1]), "=f"(d[2]), "=f"(d[3])
        : "r"(a0), "r"(a1), "r"(a2), "r"(a3), "r"(b0), "r"(b1),
          "f"(0.f), "f"(0.f), "f"(0.f), "f"(0.f));
}

// ---------------- init: zero logits + agree partials ----------------
__global__ void zero_init_kernel() {
    int i = blockIdx.x * blockDim.x + threadIdx.x;   // 0 .. 3*73728-1
    if (i < P_ * 32)            g_logits[i] = 0.f;
    else if (i < 2 * P_ * 32)   g_agree[0][i - P_ * 32] = 0.f;
    else                        g_agree[1][i - 2 * P_ * 32] = 0.f;
}

// ---------------- u = squash(caps) over D1 -> g_uh[p][b][k'] ----------------
__global__ void squash_u_kernel(const float* __restrict__ caps) {
    int gid = blockIdx.x * blockDim.x + threadIdx.x;   // p*64+b
    int p = gid >> 6, b = gid & 63;
    const float4* src = (const float4*)(caps + ((size_t)b * P_ + p) * 16);
    float4 a0 = src[0], a1 = src[1], a2 = src[2], a3 = src[3];
    float x[16] = {a0.x,a0.y,a0.z,a0.w, a1.x,a1.y,a1.z,a1.w,
                   a2.x,a2.y,a2.z,a2.w, a3.x,a3.y,a3.z,a3.w};
    float sq = 0.f;
    #pragma unroll
    for (int k = 0; k < 16; k++) sq += x[k] * x[k];
    float sc = (sq / (1.f + sq)) / sqrtf(sq + EPSQ);
    __half h[16];
    #pragma unroll
    for (int k = 0; k < 16; k++) h[kperm(k)] = __float2half(x[k] * sc);
    uint4* dst = (uint4*)(g_uh + (size_t)gid * 16);
    dst[0] = ((uint4*)h)[0];
    dst[1] = ((uint4*)h)[1];
}

// ---------------- W fp32 -> fp16 k-permuted ----------------
__global__ void convert_w_kernel(const float* __restrict__ W) {
    int gid = blockIdx.x * blockDim.x + threadIdx.x;   // (p,sd)
    const float4* src = (const float4*)(W + (size_t)gid * 16);
    float4 f0 = src[0], f1 = src[1], f2 = src[2], f3 = src[3];
    float x[16] = {f0.x,f0.y,f0.z,f0.w, f1.x,f1.y,f1.z,f1.w,
                   f2.x,f2.y,f2.z,f2.w, f3.x,f3.y,f3.z,f3.w};
    __half h[16];
    #pragma unroll
    for (int k = 0; k < 16; k++) h[kperm(k)] = __float2half(x[k]);
    uint4* dst = (uint4*)(g_Wh + (size_t)gid * 16);
    dst[0] = ((uint4*)h)[0];
    dst[1] = ((uint4*)h)[1];
}

// ---------------- softmax: fold agree partials into logits, then softmax ----------------
__global__ void softmax_fold_kernel() {
    int p    = blockIdx.x * 8 + (threadIdx.x >> 5);
    int lane = threadIdx.x & 31;
    int i = p * 32 + lane;
    float x = g_logits[i] + g_agree[0][i] + g_agree[1][i];
    g_logits[i] = x;
    float m = x;
    #pragma unroll
    for (int o = 16; o; o >>= 1) m = fmaxf(m, __shfl_xor_sync(0xffffffffu, m, o));
    float e = expf(x - m);
    float sum = e;
    #pragma unroll
    for (int o = 16; o; o >>= 1) sum += __shfl_xor_sync(0xffffffffu, sum, o);
    g_rw[i] = e / sum;
}

// ---------------- fused ws: partial[chunk] = sum_{p in chunk} rw*(W_p @ u_p^T) ----------------
// grid (8, NCH), 256 thr, 2 CTAs/SM. Software-pipelined (prefetch W+u of p+1).
__global__ void __launch_bounds__(256, 2) ws_kernel() {
    int tid = threadIdx.x, wid = tid >> 5, lane = tid & 31;
    int r = lane >> 2, q = lane & 3;
    int sdb = blockIdx.x, chunk = blockIdx.y;
    int s_w = sdb * 4 + (wid >> 1);
    int sd0 = sdb * 128 + wid * 16;

    float acc[8][4];
    #pragma unroll
    for (int j = 0; j < 8; j++)
        acc[j][0] = acc[j][1] = acc[j][2] = acc[j][3] = 0.f;

    const __half* wbase = g_Wh + (size_t)(sd0 + r) * 16 + 4 * q;
    const __half* ubase = g_uh + (size_t)r * 16 + 4 * q;
    int p0 = chunk * 64;

    // prologue: load iteration 0 operands
    uint2 ca0, ca1, cb[8]; float crw;
    {
        const __half* wp = wbase + (size_t)p0 * (SD_ * 16);
        ca0 = *(const uint2*)(wp);
        ca1 = *(const uint2*)(wp + 128);
        crw = __ldg(&g_rw[p0 * 32 + s_w]);
        const __half* up = ubase + (size_t)p0 * (64 * 16);
        #pragma unroll
        for (int j = 0; j < 8; j++) cb[j] = *(const uint2*)(up + j * 128);
    }

    for (int i = 0; i < 64; i++) {
        uint2 na0, na1, nb[8]; float nrw;
        if (i < 63) {                         // prefetch p+1 (independent of compute below)
            int pn = p0 + i + 1;
            const __half* wp = wbase + (size_t)pn * (SD_ * 16);
            na0 = *(const uint2*)(wp);
            na1 = *(const uint2*)(wp + 128);
            nrw = __ldg(&g_rw[pn * 32 + s_w]);
            const __half* up = ubase + (size_t)pn * (64 * 16);
            #pragma unroll
            for (int j = 0; j < 8; j++) nb[j] = *(const uint2*)(up + j * 128);
        }
        #pragma unroll
        for (int j = 0; j < 8; j++) {
            float d[4];
            hmma16816(d, ca0.x, ca1.x, ca0.y, ca1.y, cb[j].x, cb[j].y);
            acc[j][0] += crw * d[0]; acc[j][1] += crw * d[1];
            acc[j][2] += crw * d[2]; acc[j][3] += crw * d[3];
        }
        ca0 = na0; ca1 = na1; crw = nrw;
        #pragma unroll
        for (int j = 0; j < 8; j++) cb[j] = nb[j];
    }

    float* dst = g_wspart + (size_t)chunk * (SD_ * B_);
    #pragma unroll
    for (int j = 0; j < 8; j++) {
        int b = j * 8 + 2 * q;
        *(float2*)&dst[(sd0 + r    ) * 64 + b] = make_float2(acc[j][0], acc[j][1]);
        *(float2*)&dst[(sd0 + r + 8) * 64 + b] = make_float2(acc[j][2], acc[j][3]);
    }
}

// ---------------- reduce partials -> g_ws ----------------
__global__ void reduce_ws_kernel() {
    int t = blockIdx.x * blockDim.x + threadIdx.x;    // 0..16383 (float4 units)
    const float4* p4 = (const float4*)g_wspart;
    float4 a = p4[t];
    #pragma unroll 5
    for (int c = 1; c < NCH; c++) {
        float4 v = p4[(size_t)c * 16384 + t];
        a.x += v.x; a.y += v.y; a.z += v.z; a.w += v.w;
    }
    ((float4*)g_ws)[t] = a;
}

// ---------------- v = squash(ws) over D2 ----------------
__global__ void squash_v_kernel() {
    int gid = blockIdx.x * blockDim.x + threadIdx.x;   // 0..2047
    int s = gid >> 6, b = gid & 63;
    float x[32]; float sq = 0.f;
    #pragma unroll
    for (int d = 0; d < 32; d++) { x[d] = g_ws[(s * 32 + d) * B_ + b]; sq += x[d] * x[d]; }
    float sc = (sq / (1.f + sq)) / sqrtf(sq + EPSQ);
    #pragma unroll
    for (int d = 0; d < 32; d++) g_v[(s * 32 + d) * B_ + b] = x[d] * sc;
}

// ---------------- fused agree: partial[parity][p][s] = (1/B) sum preds.v ----------------
__global__ void __launch_bounds__(256, 2) agree_kernel() {
    int tid = threadIdx.x, wid = tid >> 5, lane = tid & 31;
    int r = lane >> 2, q = lane & 3;
    int sdb = blockIdx.x, chunk = blockIdx.y;
    int s_w = sdb * 4 + (wid >> 1);
    int sd0 = sdb * 128 + wid * 16;

    // v slice in fragment layout (register-resident)
    float vf[8][4];
    #pragma unroll
    for (int j = 0; j < 8; j++) {
        int b = j * 8 + 2 * q;
        float2 v0 = *(const float2*)&g_v[(sd0 + r    ) * 64 + b];
        float2 v1 = *(const float2*)&g_v[(sd0 + r + 8) * 64 + b];
        vf[j][0] = v0.x; vf[j][1] = v0.y; vf[j][2] = v1.x; vf[j][3] = v1.y;
    }

    const __half* wbase = g_Wh + (size_t)(sd0 + r) * 16 + 4 * q;
    const __half* ubase = g_uh + (size_t)r * 16 + 4 * q;
    int p0 = chunk * 64;
    float* out = &g_agree[wid & 1][0];

    uint2 ca0, ca1, cb[8];
    {
        const __half* wp = wbase + (size_t)p0 * (SD_ * 16);
        ca0 = *(const uint2*)(wp);
        ca1 = *(const uint2*)(wp + 128);
        const __half* up = ubase + (size_t)p0 * (64 * 16);
        #pragma unroll
        for (int j = 0; j < 8; j++) cb[j] = *(const uint2*)(up + j * 128);
    }

    for (int i = 0; i < 64; i++) {
        uint2 na0, na1, nb[8];
        if (i < 63) {
            int pn = p0 + i + 1;
            const __half* wp = wbase + (size_t)pn * (SD_ * 16);
            na0 = *(const uint2*)(wp);
            na1 = *(const uint2*)(wp + 128);
            const __half* up = ubase + (size_t)pn * (64 * 16);
            #pragma unroll
            for (int j = 0; j < 8; j++) nb[j] = *(const uint2*)(up + j * 128);
        }
        float s = 0.f;
        #pragma unroll
        for (int j = 0; j < 8; j++) {
            float d[4];
            hmma16816(d, ca0.x, ca1.x, ca0.y, ca1.y, cb[j].x, cb[j].y);
            s += d[0] * vf[j][0] + d[1] * vf[j][1] + d[2] * vf[j][2] + d[3] * vf[j][3];
        }
        #pragma unroll
        for (int o = 16; o; o >>= 1) s += __shfl_xor_sync(0xffffffffu, s, o);
        if (lane == 0) out[(p0 + i) * 32 + s_w] = s * (1.f / 64.f);
        ca0 = na0; ca1 = na1;
        #pragma unroll
        for (int j = 0; j < 8; j++) cb[j] = nb[j];
    }
}

// ---------------- final squash -> out[b][s][d] ----------------
__global__ void final_kernel(float* __restrict__ out) {
    int gid = blockIdx.x * blockDim.x + threadIdx.x;
    int s = gid >> 6, b = gid & 63;
    float x[32]; float sq = 0.f;
    #pragma unroll
    for (int d = 0; d < 32; d++) { x[d] = g_ws[(s * 32 + d) * B_ + b]; sq += x[d] * x[d]; }
    float sc = (sq / (1.f + sq)) / sqrtf(sq + EPSQ);
    #pragma unroll
    for (int d = 0; d < 32; d++) out[(b * 32 + s) * 32 + d] = x[d] * sc;
}

// ---------------- launch ----------------
extern "C" void kernel_launch(void* const* d_in, const int* in_sizes, int n_in,
                              void* d_out, int out_size) {
    const float* caps = (const float*)d_in[0];   // [B,P,D1] fp32
    const float* W    = (const float*)d_in[1];   // [P,S,D2,D1] fp32
    float* out        = (float*)d_out;           // [B,1,S,D2] fp32

    zero_init_kernel<<<216, 1024>>>();                  // 3 * P_ * 32 = 221184
    squash_u_kernel<<<(P_ * B_) / 256, 256>>>(caps);
    convert_w_kernel<<<(P_ * SD_) / 256, 256>>>(W);

    for (int it = 0; it < 3; it++) {
        softmax_fold_kernel<<<P_ / 8, 256>>>();
        ws_kernel<<<dim3(8, NCH), 256>>>();
        reduce_ws_kernel<<<64, 256>>>();
        if (it < 2) {
            squash_v_kernel<<<8, 256>>>();
            agree_kernel<<<dim3(8, NCH), 256>>>();
        } else {
            final_kernel<<<8, 256>>>(out);
        }
    }
}